// round 2
// baseline (speedup 1.0000x reference)
#include <cuda_runtime.h>
#include <cuda_bf16.h>
#include <math.h>

// Problem constants
#define BATCH 4
#define TSEQ  1024
#define DMODEL 512
#define NCLUST 8
#define NHEAD 8
#define HD 64
#define NTOK (BATCH * TSEQ)          // 4096
#define QKVF (3 * DMODEL)            // 1536
#define SCALE 0.125f                 // 1/sqrt(64)

// Scratch (allocation-free rule: __device__ globals)
__device__ int   g_assign[NTOK];
__device__ float g_Q[BATCH * NHEAD * TSEQ * HD];   // [(b*H+h)*T + t]*HD + d
__device__ float g_K[BATCH * NHEAD * TSEQ * HD];
__device__ float g_V[BATCH * NHEAD * TSEQ * HD];
__device__ float g_O[NTOK * DMODEL];               // attention out, [token][D]

// ---------------------------------------------------------------------------
// Kernel 1: cluster assignment  assign[t] = argmax_c (X[t]·Wc[c] + bc[c])
// One warp per token; Wc (8x512 = 16KB) staged in smem.
// ---------------------------------------------------------------------------
__global__ __launch_bounds__(256) void assign_kernel(const float* __restrict__ X,
                                                     const float* __restrict__ Wc,
                                                     const float* __restrict__ bc) {
    __shared__ float wcs[NCLUST * DMODEL];
    __shared__ float bcs[NCLUST];
    for (int i = threadIdx.x; i < NCLUST * DMODEL; i += blockDim.x) wcs[i] = Wc[i];
    if (threadIdx.x < NCLUST) bcs[threadIdx.x] = bc[threadIdx.x];
    __syncthreads();

    int warp = threadIdx.x >> 5;
    int lane = threadIdx.x & 31;
    int token = blockIdx.x * 8 + warp;
    if (token >= NTOK) return;

    const float* x = X + (size_t)token * DMODEL;
    float xr[16];
#pragma unroll
    for (int i = 0; i < 16; i++) xr[i] = x[lane + i * 32];

    float best = -1e30f;
    int bestc = 0;
#pragma unroll
    for (int c = 0; c < NCLUST; c++) {
        const float* w = wcs + c * DMODEL;
        float p = 0.f;
#pragma unroll
        for (int i = 0; i < 16; i++) p = fmaf(xr[i], w[lane + i * 32], p);
#pragma unroll
        for (int o = 16; o > 0; o >>= 1) p += __shfl_xor_sync(0xffffffffu, p, o);
        p += bcs[c];
        if (p > best) { best = p; bestc = c; }   // strict > : first-max tiebreak
    }
    if (lane == 0) g_assign[token] = bestc;
}

// ---------------------------------------------------------------------------
// Kernel 2: QKV projection. C[4096,1536] = X[4096,512] @ Win[1536,512]^T + bin
// 128x128 block tile, BK=16, 8x8 micro-tile. Epilogue scatters into
// g_Q/g_K/g_V in [B,H,T,64] layout.
// ---------------------------------------------------------------------------
__global__ __launch_bounds__(256) void qkv_kernel(const float* __restrict__ A,
                                                  const float* __restrict__ Bm,
                                                  const float* __restrict__ bin) {
    const int K = DMODEL;
    __shared__ float As[128][17];
    __shared__ float Bs[128][17];
    int tx = threadIdx.x, ty = threadIdx.y;
    int tid = ty * 16 + tx;
    int row0 = blockIdx.y * 128;
    int col0 = blockIdx.x * 128;

    float acc[8][8];
#pragma unroll
    for (int i = 0; i < 8; i++)
#pragma unroll
        for (int j = 0; j < 8; j++) acc[i][j] = 0.f;

    for (int k0 = 0; k0 < K; k0 += 16) {
#pragma unroll
        for (int ld = 0; ld < 2; ld++) {
            int idx = tid + ld * 256;                // 0..511 float4 slots
            int r = idx >> 2, c4 = (idx & 3) * 4;
            float4 va = *(const float4*)(A + (size_t)(row0 + r) * K + k0 + c4);
            As[r][c4] = va.x; As[r][c4 + 1] = va.y; As[r][c4 + 2] = va.z; As[r][c4 + 3] = va.w;
            float4 vb = *(const float4*)(Bm + (size_t)(col0 + r) * K + k0 + c4);
            Bs[r][c4] = vb.x; Bs[r][c4 + 1] = vb.y; Bs[r][c4 + 2] = vb.z; Bs[r][c4 + 3] = vb.w;
        }
        __syncthreads();
#pragma unroll
        for (int kk = 0; kk < 16; kk++) {
            float a[8], b[8];
#pragma unroll
            for (int i = 0; i < 8; i++) a[i] = As[ty + i * 16][kk];
#pragma unroll
            for (int j = 0; j < 8; j++) b[j] = Bs[tx + j * 16][kk];
#pragma unroll
            for (int i = 0; i < 8; i++)
#pragma unroll
                for (int j = 0; j < 8; j++) acc[i][j] = fmaf(a[i], b[j], acc[i][j]);
        }
        __syncthreads();
    }

#pragma unroll
    for (int i = 0; i < 8; i++) {
        int t = row0 + ty + i * 16;
        int b = t >> 10, tt = t & 1023;
#pragma unroll
        for (int j = 0; j < 8; j++) {
            int f = col0 + tx + j * 16;
            float v = acc[i][j] + bin[f];
            int type = f >> 9;              // 0=q 1=k 2=v
            int h = (f >> 6) & 7;
            int idx = f & 63;
            float* dst = (type == 0) ? g_Q : (type == 1) ? g_K : g_V;
            dst[(((size_t)(b * NHEAD + h)) * TSEQ + tt) * HD + idx] = v;
        }
    }
}

// ---------------------------------------------------------------------------
// Kernel 3: clustered flash attention (fp32, online softmax).
// grid (T/128, B*H), 256 threads; a PAIR of threads owns one query row,
// each half owns 32 of the 64 head dims (halves register pressure vs one
// thread per query: ~110 live regs, no spills, 2x parallelism).
// Score = partial dot + SHFL.BFLY(1) combine.
// Mismatched keys use score s0 = q·k0 (k0 = bin_k) and value v0 = bin_v,
// aggregated into w0 (exact softmax denominator over all T keys).
// ---------------------------------------------------------------------------
__global__ __launch_bounds__(256, 2) void attn_kernel(const float* __restrict__ bin) {
    __shared__ float Ks[32 * HD];
    __shared__ float Vs[32 * HD];
    __shared__ float k0s[HD];
    __shared__ float v0s[HD];
    __shared__ int   ka[32];

    int bh = blockIdx.y;
    int b = bh >> 3;
    int h = bh & 7;
    int tid = threadIdx.x;
    int half = tid & 1;                 // which 32 dims of the head this thread owns
    int qi = tid >> 1;                  // query row within the block (0..127)
    int q = blockIdx.x * 128 + qi;

    if (tid < HD) {
        k0s[tid] = bin[DMODEL + h * HD + tid];
        v0s[tid] = bin[2 * DMODEL + h * HD + tid];
    }
    __syncthreads();

    // load this thread's 32-dim half of the query row
    float qreg[32];
    {
        const float4* qp = (const float4*)(g_Q + (((size_t)bh * TSEQ) + q) * HD + half * 32);
#pragma unroll
        for (int i = 0; i < 8; i++) {
            float4 v = qp[i];
            qreg[4 * i] = v.x; qreg[4 * i + 1] = v.y; qreg[4 * i + 2] = v.z; qreg[4 * i + 3] = v.w;
        }
    }
    int myc = g_assign[b * TSEQ + q];

    float s0;
    {
        float p = 0.f;
#pragma unroll
        for (int d = 0; d < 32; d++) p = fmaf(qreg[d], k0s[half * 32 + d], p);
        p += __shfl_xor_sync(0xffffffffu, p, 1);
        s0 = p * SCALE;
    }

    float m = -1e30f, l = 0.f, w0 = 0.f;
    float accum[32];
#pragma unroll
    for (int d = 0; d < 32; d++) accum[d] = 0.f;

    const float* Kb = g_K + (size_t)bh * TSEQ * HD;
    const float* Vb = g_V + (size_t)bh * TSEQ * HD;
    const int* ab = g_assign + b * TSEQ;

    for (int kt = 0; kt < TSEQ; kt += 32) {
        __syncthreads();
        {
            const float4* ksrc = (const float4*)(Kb + (size_t)kt * HD);
            const float4* vsrc = (const float4*)(Vb + (size_t)kt * HD);
            float4* kdst = (float4*)Ks;
            float4* vdst = (float4*)Vs;
#pragma unroll
            for (int i = tid; i < 512; i += 256) { kdst[i] = ksrc[i]; vdst[i] = vsrc[i]; }
            if (tid < 32) ka[tid] = ab[kt + tid];
        }
        __syncthreads();

        float s[32];
        unsigned matchmask = 0u;
        float tmax = -1e30f;
#pragma unroll
        for (int j = 0; j < 32; j++) {
            const float4* kr = (const float4*)(Ks + j * HD + half * 32);
            float p = 0.f;
#pragma unroll
            for (int i = 0; i < 8; i++) {
                float4 kv = kr[i];
                p = fmaf(qreg[4 * i],     kv.x, p);
                p = fmaf(qreg[4 * i + 1], kv.y, p);
                p = fmaf(qreg[4 * i + 2], kv.z, p);
                p = fmaf(qreg[4 * i + 3], kv.w, p);
            }
            p += __shfl_xor_sync(0xffffffffu, p, 1);
            float sj = p * SCALE;
            if (ka[j] == myc) matchmask |= (1u << j);
            else sj = s0;
            s[j] = sj;
            tmax = fmaxf(tmax, sj);
        }

        float newm = fmaxf(m, tmax);
        float corr = __expf(m - newm);
        l *= corr;
        w0 *= corr;
#pragma unroll
        for (int d = 0; d < 32; d++) accum[d] *= corr;
        m = newm;

#pragma unroll
        for (int j = 0; j < 32; j++) {
            float p = __expf(s[j] - newm);
            l += p;
            float pm = (matchmask >> j) & 1u ? p : 0.f;
            w0 += p - pm;
            const float4* vr = (const float4*)(Vs + j * HD + half * 32);
#pragma unroll
            for (int i = 0; i < 8; i++) {
                float4 vv = vr[i];
                accum[4 * i]     = fmaf(pm, vv.x, accum[4 * i]);
                accum[4 * i + 1] = fmaf(pm, vv.y, accum[4 * i + 1]);
                accum[4 * i + 2] = fmaf(pm, vv.z, accum[4 * i + 2]);
                accum[4 * i + 3] = fmaf(pm, vv.w, accum[4 * i + 3]);
            }
        }
    }

    float inv = 1.f / l;
    float* op = g_O + (size_t)(b * TSEQ + q) * DMODEL + h * HD + half * 32;
#pragma unroll
    for (int i = 0; i < 8; i++) {
        float4 v;
        v.x = (accum[4 * i]     + w0 * v0s[half * 32 + 4 * i])     * inv;
        v.y = (accum[4 * i + 1] + w0 * v0s[half * 32 + 4 * i + 1]) * inv;
        v.z = (accum[4 * i + 2] + w0 * v0s[half * 32 + 4 * i + 2]) * inv;
        v.w = (accum[4 * i + 3] + w0 * v0s[half * 32 + 4 * i + 3]) * inv;
        ((float4*)op)[i] = v;
    }
}

// ---------------------------------------------------------------------------
// Kernel 4: output projection. out[4096,512] = g_O @ Wout[512,512]^T + bout
// ---------------------------------------------------------------------------
__global__ __launch_bounds__(256) void proj_kernel(const float* __restrict__ Bm,
                                                   const float* __restrict__ bout,
                                                   float* __restrict__ out) {
    const int K = DMODEL;
    __shared__ float As[128][17];
    __shared__ float Bs[128][17];
    int tx = threadIdx.x, ty = threadIdx.y;
    int tid = ty * 16 + tx;
    int row0 = blockIdx.y * 128;
    int col0 = blockIdx.x * 128;
    const float* A = g_O;

    float acc[8][8];
#pragma unroll
    for (int i = 0; i < 8; i++)
#pragma unroll
        for (int j = 0; j < 8; j++) acc[i][j] = 0.f;

    for (int k0 = 0; k0 < K; k0 += 16) {
#pragma unroll
        for (int ld = 0; ld < 2; ld++) {
            int idx = tid + ld * 256;
            int r = idx >> 2, c4 = (idx & 3) * 4;
            float4 va = *(const float4*)(A + (size_t)(row0 + r) * K + k0 + c4);
            As[r][c4] = va.x; As[r][c4 + 1] = va.y; As[r][c4 + 2] = va.z; As[r][c4 + 3] = va.w;
            float4 vb = *(const float4*)(Bm + (size_t)(col0 + r) * K + k0 + c4);
            Bs[r][c4] = vb.x; Bs[r][c4 + 1] = vb.y; Bs[r][c4 + 2] = vb.z; Bs[r][c4 + 3] = vb.w;
        }
        __syncthreads();
#pragma unroll
        for (int kk = 0; kk < 16; kk++) {
            float a[8], bb[8];
#pragma unroll
            for (int i = 0; i < 8; i++) a[i] = As[ty + i * 16][kk];
#pragma unroll
            for (int j = 0; j < 8; j++) bb[j] = Bs[tx + j * 16][kk];
#pragma unroll
            for (int i = 0; i < 8; i++)
#pragma unroll
                for (int j = 0; j < 8; j++) acc[i][j] = fmaf(a[i], bb[j], acc[i][j]);
        }
        __syncthreads();
    }

#pragma unroll
    for (int i = 0; i < 8; i++) {
        int t = row0 + ty + i * 16;
#pragma unroll
        for (int j = 0; j < 8; j++) {
            int f = col0 + tx + j * 16;
            out[(size_t)t * DMODEL + f] = acc[i][j] + bout[f];
        }
    }
}

// ---------------------------------------------------------------------------
extern "C" void kernel_launch(void* const* d_in, const int* in_sizes, int n_in,
                              void* d_out, int out_size) {
    const float* X    = (const float*)d_in[0];   // [4, 1024, 512]
    const float* Wc   = (const float*)d_in[1];   // [8, 512]
    const float* bc   = (const float*)d_in[2];   // [8]
    const float* Win  = (const float*)d_in[3];   // [1536, 512]
    const float* bin  = (const float*)d_in[4];   // [1536]
    const float* Wout = (const float*)d_in[5];   // [512, 512]
    const float* bout = (const float*)d_in[6];   // [512]
    float* out = (float*)d_out;                  // [4, 1024, 512]

    assign_kernel<<<NTOK / 8, 256>>>(X, Wc, bc);
    qkv_kernel<<<dim3(QKVF / 128, NTOK / 128), dim3(16, 16)>>>(X, Win, bin);
    attn_kernel<<<dim3(TSEQ / 128, BATCH * NHEAD), 256>>>(bin);
    proj_kernel<<<dim3(DMODEL / 128, NTOK / 128), dim3(16, 16)>>>(Wout, bout, out);
}

// round 7
// speedup vs baseline: 1.8415x; 1.8415x over previous
#include <cuda_runtime.h>
#include <cuda_bf16.h>
#include <math.h>

// Problem constants
#define BATCH 4
#define TSEQ  1024
#define DMODEL 512
#define NCLUST 8
#define NHEAD 8
#define HD 64
#define NTOK (BATCH * TSEQ)          // 4096
#define QKVF (3 * DMODEL)            // 1536
#define SCALE 0.125f                 // 1/sqrt(64)

// Scratch (__device__ globals; allocation-free rule)
__device__ int   g_assign[NTOK];
__device__ int   g_ccount[BATCH * NCLUST];
__device__ int   g_clist[BATCH * NCLUST * TSEQ];
__device__ float g_Q[BATCH * NHEAD * TSEQ * HD];
__device__ float g_K[BATCH * NHEAD * TSEQ * HD];
__device__ float g_V[BATCH * NHEAD * TSEQ * HD];
__device__ float g_O[NTOK * DMODEL];

// ---------------------------------------------------------------------------
// Kernel 1: cluster assignment  assign[t] = argmax_c (X[t]·Wc[c] + bc[c])
// (measured working in R2)
// ---------------------------------------------------------------------------
__global__ __launch_bounds__(256) void assign_kernel(const float* __restrict__ X,
                                                     const float* __restrict__ Wc,
                                                     const float* __restrict__ bc) {
    __shared__ float wcs[NCLUST * DMODEL];
    __shared__ float bcs[NCLUST];
    for (int i = threadIdx.x; i < NCLUST * DMODEL; i += blockDim.x) wcs[i] = Wc[i];
    if (threadIdx.x < NCLUST) bcs[threadIdx.x] = bc[threadIdx.x];
    __syncthreads();

    int warp = threadIdx.x >> 5;
    int lane = threadIdx.x & 31;
    int token = blockIdx.x * 8 + warp;
    if (token >= NTOK) return;

    const float* x = X + (size_t)token * DMODEL;
    float xr[16];
#pragma unroll
    for (int i = 0; i < 16; i++) xr[i] = x[lane + i * 32];

    float best = -1e30f;
    int bestc = 0;
#pragma unroll
    for (int c = 0; c < NCLUST; c++) {
        const float* w = wcs + c * DMODEL;
        float p = 0.f;
#pragma unroll
        for (int i = 0; i < 16; i++) p = fmaf(xr[i], w[lane + i * 32], p);
#pragma unroll
        for (int o = 16; o > 0; o >>= 1) p += __shfl_xor_sync(0xffffffffu, p, o);
        p += bcs[c];
        if (p > best) { best = p; bestc = c; }   // strict > : first-max tiebreak
    }
    if (lane == 0) g_assign[token] = bestc;
}

// ---------------------------------------------------------------------------
// Kernel 2: deterministic per-(batch,cluster) token lists.
// Ballot + prefix scan; token order preserved; no atomics.
// ---------------------------------------------------------------------------
__global__ __launch_bounds__(1024) void build_lists_kernel() {
    __shared__ int wtot[NCLUST][32];
    int b = blockIdx.x;
    int t = threadIdx.x;
    int wid = t >> 5, lane = t & 31;
    int c = g_assign[b * TSEQ + t];

    int myrank = 0;
#pragma unroll
    for (int c8 = 0; c8 < NCLUST; c8++) {
        unsigned m = __ballot_sync(0xffffffffu, c == c8);
        if (lane == 0) wtot[c8][wid] = __popc(m);
        if (c8 == c) myrank = __popc(m & ((1u << lane) - 1u));
    }
    __syncthreads();

    int prefix = 0;
    for (int w = 0; w < wid; w++) prefix += wtot[c][w];
    g_clist[(b * NCLUST + c) * TSEQ + prefix + myrank] = t;

    if (t < NCLUST) {
        int tot = 0;
#pragma unroll
        for (int w = 0; w < 32; w++) tot += wtot[t][w];
        g_ccount[b * NCLUST + t] = tot;
    }
}

// ---------------------------------------------------------------------------
// Kernel 3: QKV projection (measured-working R2 SGEMM).
// C[4096,1536] = X[4096,512] @ Win[1536,512]^T + bin, scatter into [B,H,T,64]
// ---------------------------------------------------------------------------
__global__ __launch_bounds__(256) void qkv_kernel(const float* __restrict__ A,
                                                  const float* __restrict__ Bm,
                                                  const float* __restrict__ bin) {
    const int K = DMODEL;
    __shared__ float As[128][17];
    __shared__ float Bs[128][17];
    int tx = threadIdx.x, ty = threadIdx.y;
    int tid = ty * 16 + tx;
    int row0 = blockIdx.y * 128;
    int col0 = blockIdx.x * 128;

    float acc[8][8];
#pragma unroll
    for (int i = 0; i < 8; i++)
#pragma unroll
        for (int j = 0; j < 8; j++) acc[i][j] = 0.f;

    for (int k0 = 0; k0 < K; k0 += 16) {
#pragma unroll
        for (int ld = 0; ld < 2; ld++) {
            int idx = tid + ld * 256;
            int r = idx >> 2, c4 = (idx & 3) * 4;
            float4 va = *(const float4*)(A + (size_t)(row0 + r) * K + k0 + c4);
            As[r][c4] = va.x; As[r][c4 + 1] = va.y; As[r][c4 + 2] = va.z; As[r][c4 + 3] = va.w;
            float4 vb = *(const float4*)(Bm + (size_t)(col0 + r) * K + k0 + c4);
            Bs[r][c4] = vb.x; Bs[r][c4 + 1] = vb.y; Bs[r][c4 + 2] = vb.z; Bs[r][c4 + 3] = vb.w;
        }
        __syncthreads();
#pragma unroll
        for (int kk = 0; kk < 16; kk++) {
            float a[8], b[8];
#pragma unroll
            for (int i = 0; i < 8; i++) a[i] = As[ty + i * 16][kk];
#pragma unroll
            for (int j = 0; j < 8; j++) b[j] = Bs[tx + j * 16][kk];
#pragma unroll
            for (int i = 0; i < 8; i++)
#pragma unroll
                for (int j = 0; j < 8; j++) acc[i][j] = fmaf(a[i], b[j], acc[i][j]);
        }
        __syncthreads();
    }

#pragma unroll
    for (int i = 0; i < 8; i++) {
        int t = row0 + ty + i * 16;
        int b = t >> 10, tt = t & 1023;
#pragma unroll
        for (int j = 0; j < 8; j++) {
            int f = col0 + tx + j * 16;
            float v = acc[i][j] + bin[f];
            int type = f >> 9;              // 0=q 1=k 2=v
            int h = (f >> 6) & 7;
            int idx = f & 63;
            float* dst = (type == 0) ? g_Q : (type == 1) ? g_K : g_V;
            dst[(((size_t)(b * NHEAD + h)) * TSEQ + tt) * HD + idx] = v;
        }
    }
}

// ---------------------------------------------------------------------------
// Kernel 4: clustered flash attention. Each query attends only to its own
// cluster's keys (gathered via g_clist); the T-n mismatched keys all share
// score s0 = q·k0 (k0 = bin_k) and value v0 = bin_v (masked-token QKV equal
// the in-proj bias), contributing the closed-form term (T-n)*exp(s0-m)*v0.
// Thread pair per query row (each half owns 32 dims); m initialized to s0.
// grid: (ceil(T/128)=8, NHEAD, BATCH*NCLUST), 256 threads.
// ---------------------------------------------------------------------------
__global__ __launch_bounds__(256, 2) void attn_kernel(const float* __restrict__ bin) {
    __shared__ float Ks[32 * HD];
    __shared__ float Vs[32 * HD];
    __shared__ float k0s[HD];
    __shared__ float v0s[HD];
    __shared__ int   klist[32];

    int bc = blockIdx.z;
    int b = bc >> 3;
    int h = blockIdx.y;
    int n = g_ccount[bc];
    int q0 = blockIdx.x * 128;
    if (q0 >= n) return;                    // uniform across CTA

    int tid = threadIdx.x;
    int half = tid & 1;
    int qi = tid >> 1;
    int qvalid = (q0 + qi) < n;
    const int* list = g_clist + bc * TSEQ;
    int qtok = list[qvalid ? (q0 + qi) : 0];

    if (tid < HD) {
        k0s[tid] = bin[DMODEL + h * HD + tid];
        v0s[tid] = bin[2 * DMODEL + h * HD + tid];
    }
    __syncthreads();

    int bh = b * NHEAD + h;
    const float4* Kb4 = (const float4*)(g_K + (size_t)bh * TSEQ * HD);
    const float4* Vb4 = (const float4*)(g_V + (size_t)bh * TSEQ * HD);

    float qreg[32];
    {
        const float4* qp = (const float4*)(g_Q + ((size_t)bh * TSEQ + qtok) * HD + half * 32);
#pragma unroll
        for (int i = 0; i < 8; i++) {
            float4 v = qp[i];
            qreg[4 * i] = v.x; qreg[4 * i + 1] = v.y; qreg[4 * i + 2] = v.z; qreg[4 * i + 3] = v.w;
        }
    }

    float s0;
    {
        float p = 0.f;
#pragma unroll
        for (int d = 0; d < 32; d++) p = fmaf(qreg[d], k0s[half * 32 + d], p);
        p += __shfl_xor_sync(0xffffffffu, p, 1);
        s0 = p * SCALE;
    }

    float m = s0, l = 0.f;
    float accum[32];
#pragma unroll
    for (int d = 0; d < 32; d++) accum[d] = 0.f;

    for (int kt = 0; kt < n; kt += 32) {
        int kn = n - kt; if (kn > 32) kn = 32;
        __syncthreads();
        if (tid < 32) klist[tid] = (kt + tid < n) ? list[kt + tid] : -1;
        __syncthreads();
        // gather K/V rows (zero-fill pad rows)
#pragma unroll
        for (int it = 0; it < 2; it++) {
            int idx = tid + it * 256;       // 0..511: row = idx>>4, f4 = idx&15
            int row = idx >> 4, f4 = idx & 15;
            int tok = klist[row];
            float4 kv = make_float4(0.f, 0.f, 0.f, 0.f), vv = kv;
            if (tok >= 0) { kv = Kb4[(size_t)tok * 16 + f4]; vv = Vb4[(size_t)tok * 16 + f4]; }
            ((float4*)Ks)[row * 16 + f4] = kv;
            ((float4*)Vs)[row * 16 + f4] = vv;
        }
        __syncthreads();

        float s[32];
        float tmax = m;
#pragma unroll
        for (int j = 0; j < 32; j++) {
            const float4* kr = (const float4*)(Ks + j * HD + half * 32);
            float p = 0.f;
#pragma unroll
            for (int i = 0; i < 8; i++) {
                float4 kv = kr[i];
                p = fmaf(qreg[4 * i],     kv.x, p);
                p = fmaf(qreg[4 * i + 1], kv.y, p);
                p = fmaf(qreg[4 * i + 2], kv.z, p);
                p = fmaf(qreg[4 * i + 3], kv.w, p);
            }
            p += __shfl_xor_sync(0xffffffffu, p, 1);
            float sj = (j < kn) ? p * SCALE : -1e30f;
            s[j] = sj;
            tmax = fmaxf(tmax, sj);
        }

        float corr = __expf(m - tmax);
        l *= corr;
#pragma unroll
        for (int d = 0; d < 32; d++) accum[d] *= corr;
        m = tmax;

#pragma unroll
        for (int j = 0; j < 32; j++) {
            float p = __expf(s[j] - m);
            l += p;
            const float4* vr = (const float4*)(Vs + j * HD + half * 32);
#pragma unroll
            for (int i = 0; i < 8; i++) {
                float4 vv = vr[i];
                accum[4 * i]     = fmaf(p, vv.x, accum[4 * i]);
                accum[4 * i + 1] = fmaf(p, vv.y, accum[4 * i + 1]);
                accum[4 * i + 2] = fmaf(p, vv.z, accum[4 * i + 2]);
                accum[4 * i + 3] = fmaf(p, vv.w, accum[4 * i + 3]);
            }
        }
    }

    // closed-form mismatched-key term: (T-n) keys, score s0, value v0
    float w0 = (float)(TSEQ - n) * __expf(s0 - m);
    l += w0;

    if (qvalid) {
        float inv = 1.f / l;
        float* op = g_O + (size_t)(b * TSEQ + qtok) * DMODEL + h * HD + half * 32;
#pragma unroll
        for (int i = 0; i < 8; i++) {
            float4 v;
            v.x = (accum[4 * i]     + w0 * v0s[half * 32 + 4 * i])     * inv;
            v.y = (accum[4 * i + 1] + w0 * v0s[half * 32 + 4 * i + 1]) * inv;
            v.z = (accum[4 * i + 2] + w0 * v0s[half * 32 + 4 * i + 2]) * inv;
            v.w = (accum[4 * i + 3] + w0 * v0s[half * 32 + 4 * i + 3]) * inv;
            ((float4*)op)[i] = v;
        }
    }
}

// ---------------------------------------------------------------------------
// Kernel 5: output projection (measured-working R2 SGEMM, 94us).
// out[4096,512] = g_O @ Wout[512,512]^T + bout
// ---------------------------------------------------------------------------
__global__ __launch_bounds__(256) void proj_kernel(const float* __restrict__ Bm,
                                                   const float* __restrict__ bout,
                                                   float* __restrict__ out) {
    const int K = DMODEL;
    __shared__ float As[128][17];
    __shared__ float Bs[128][17];
    int tx = threadIdx.x, ty = threadIdx.y;
    int tid = ty * 16 + tx;
    int row0 = blockIdx.y * 128;
    int col0 = blockIdx.x * 128;
    const float* A = g_O;

    float acc[8][8];
#pragma unroll
    for (int i = 0; i < 8; i++)
#pragma unroll
        for (int j = 0; j < 8; j++) acc[i][j] = 0.f;

    for (int k0 = 0; k0 < K; k0 += 16) {
#pragma unroll
        for (int ld = 0; ld < 2; ld++) {
            int idx = tid + ld * 256;
            int r = idx >> 2, c4 = (idx & 3) * 4;
            float4 va = *(const float4*)(A + (size_t)(row0 + r) * K + k0 + c4);
            As[r][c4] = va.x; As[r][c4 + 1] = va.y; As[r][c4 + 2] = va.z; As[r][c4 + 3] = va.w;
            float4 vb = *(const float4*)(Bm + (size_t)(col0 + r) * K + k0 + c4);
            Bs[r][c4] = vb.x; Bs[r][c4 + 1] = vb.y; Bs[r][c4 + 2] = vb.z; Bs[r][c4 + 3] = vb.w;
        }
        __syncthreads();
#pragma unroll
        for (int kk = 0; kk < 16; kk++) {
            float a[8], bb[8];
#pragma unroll
            for (int i = 0; i < 8; i++) a[i] = As[ty + i * 16][kk];
#pragma unroll
            for (int j = 0; j < 8; j++) bb[j] = Bs[tx + j * 16][kk];
#pragma unroll
            for (int i = 0; i < 8; i++)
#pragma unroll
                for (int j = 0; j < 8; j++) acc[i][j] = fmaf(a[i], bb[j], acc[i][j]);
        }
        __syncthreads();
    }

#pragma unroll
    for (int i = 0; i < 8; i++) {
        int t = row0 + ty + i * 16;
#pragma unroll
        for (int j = 0; j < 8; j++) {
            int f = col0 + tx + j * 16;
            out[(size_t)t * DMODEL + f] = acc[i][j] + bout[f];
        }
    }
}

// ---------------------------------------------------------------------------
extern "C" void kernel_launch(void* const* d_in, const int* in_sizes, int n_in,
                              void* d_out, int out_size) {
    const float* X    = (const float*)d_in[0];   // [4, 1024, 512]
    const float* Wc   = (const float*)d_in[1];   // [8, 512]
    const float* bc   = (const float*)d_in[2];   // [8]
    const float* Win  = (const float*)d_in[3];   // [1536, 512]
    const float* bin  = (const float*)d_in[4];   // [1536]
    const float* Wout = (const float*)d_in[5];   // [512, 512]
    const float* bout = (const float*)d_in[6];   // [512]
    float* out = (float*)d_out;                  // [4, 1024, 512]

    assign_kernel<<<NTOK / 8, 256>>>(X, Wc, bc);
    build_lists_kernel<<<BATCH, 1024>>>();
    qkv_kernel<<<dim3(QKVF / 128, NTOK / 128), dim3(16, 16)>>>(X, Win, bin);
    attn_kernel<<<dim3(8, NHEAD, BATCH * NCLUST), 256>>>(bin);
    proj_kernel<<<dim3(DMODEL / 128, NTOK / 128), dim3(16, 16)>>>(Wout, bout, out);
}